// round 1
// baseline (speedup 1.0000x reference)
#include <cuda_runtime.h>

// Problem constants
#define Bx  2
#define Sx  2048
#define Dx  1024
#define Hx  16
#define DKx 64
#define Mx  (Bx*Sx)            // 4096 rows

// Scratch (device globals: allocation-free per harness rules)
__device__ float g_q2[(size_t)Bx*Hx*Sx*DKx];   // [b,h,s,k] projected q
__device__ float g_k2[(size_t)Bx*Hx*Sx*DKx];   // [b,h,s,k] projected k
__device__ float g_v2[(size_t)Bx*Hx*Sx*DKx];   // [b,h,s,k] projected v
__device__ float g_ao[(size_t)Bx*Sx*Hx*DKx];   // [b,s,h,k] attention output (concat layout)

// ---------------------------------------------------------------------------
// GEMM: C = A[M,K] @ W[N,K]^T + bias[N]
//   which = 0/1/2 : write to g_q2/g_k2/g_v2 in [b,h,s,k] layout
//   which = 3     : write plain row-major [M,N] to Cext
//   asrc  = 1     : read A from g_ao instead of Aext
// Tiles: 128x128x16, 256 threads, 8x8 register tile per thread.
// ---------------------------------------------------------------------------
__global__ void __launch_bounds__(256) gemm_kernel(
    const float* __restrict__ Aext, const float* __restrict__ W,
    const float* __restrict__ bias, float* __restrict__ Cext,
    int which, int asrc, int N, int K)
{
    const float* A = asrc ? g_ao : Aext;
    __shared__ float As[16][132];   // transposed A tile [k][m], pad for banks
    __shared__ float Bs[16][132];   // transposed W tile [k][n]

    int tid  = threadIdx.x;
    int tx   = tid & 15;            // 0..15 (cols)
    int ty   = tid >> 4;            // 0..15 (rows)
    int brow = blockIdx.y * 128;
    int bcol = blockIdx.x * 128;
    int lrow = tid >> 2;            // 0..63
    int lc4  = (tid & 3) * 4;       // 0,4,8,12

    float acc[8][8] = {};

    for (int k0 = 0; k0 < K; k0 += 16) {
        #pragma unroll
        for (int r = 0; r < 2; r++) {
            int row = lrow + r * 64;
            float4 va = *(const float4*)&A[(size_t)(brow + row) * K + k0 + lc4];
            As[lc4+0][row] = va.x; As[lc4+1][row] = va.y;
            As[lc4+2][row] = va.z; As[lc4+3][row] = va.w;
            float4 vb = *(const float4*)&W[(size_t)(bcol + row) * K + k0 + lc4];
            Bs[lc4+0][row] = vb.x; Bs[lc4+1][row] = vb.y;
            Bs[lc4+2][row] = vb.z; Bs[lc4+3][row] = vb.w;
        }
        __syncthreads();
        #pragma unroll
        for (int kk = 0; kk < 16; kk++) {
            float a[8], b[8];
            #pragma unroll
            for (int i = 0; i < 8; i++) a[i] = As[kk][ty*8 + i];
            #pragma unroll
            for (int j = 0; j < 8; j++) b[j] = Bs[kk][tx*8 + j];
            #pragma unroll
            for (int i = 0; i < 8; i++)
                #pragma unroll
                for (int j = 0; j < 8; j++)
                    acc[i][j] += a[i] * b[j];
        }
        __syncthreads();
    }

    float* Cp = (which == 0) ? g_q2 : (which == 1) ? g_k2 : (which == 2) ? g_v2 : Cext;
    #pragma unroll
    for (int i = 0; i < 8; i++) {
        int row = brow + ty*8 + i;
        #pragma unroll
        for (int j = 0; j < 8; j++) {
            int col = bcol + tx*8 + j;
            float v = acc[i][j] + bias[col];
            if (which == 3) {
                Cp[(size_t)row * N + col] = v;
            } else {
                int b = row >> 11, s = row & 2047;     // row = b*S + s
                int h = col >> 6,  kk = col & 63;      // col = h*DK + kk
                Cp[(((size_t)(b*Hx + h)) * Sx + s) * DKx + kk] = v;
            }
        }
    }
}

// ---------------------------------------------------------------------------
// Flash attention with role swap per reference:
//   scores = v2 @ k2^T / sqrt(DK);  attn = softmax;  out = attn @ q2
// So: Q-role = v2, K-role = k2, V-role = q2.
// Per CTA: one (b,h), Br=64 query rows; stream key blocks Bc=32.
// 256 threads as 16x16; each thread: 4x2 of S tile, 4x4 of O tile.
// Output written directly in [b,s,h,k] (concat) layout to g_ao.
// ---------------------------------------------------------------------------
__global__ void __launch_bounds__(256) flash_kernel()
{
    int bh   = blockIdx.y;          // b*H + h (0..31)
    int b    = bh >> 4;
    int h    = bh & 15;
    int row0 = blockIdx.x * 64;

    const float* Qg = g_v2 + (size_t)bh * Sx * DKx;
    const float* Kg = g_k2 + (size_t)bh * Sx * DKx;
    const float* Vg = g_q2 + (size_t)bh * Sx * DKx;

    __shared__ float Qs[64][68];    // pitch 68 floats = 17 float4 (odd -> conflict-free)
    __shared__ float Ks[32][68];
    __shared__ float Vs[32][68];
    __shared__ float Ss[64][36];    // 32 cols + pad
    __shared__ float ml[64], ll[64], al_s[64];

    int tid  = threadIdx.x;
    int tx   = tid & 15;
    int ty   = tid >> 4;
    int warp = tid >> 5;
    int lane = tid & 31;

    // Load Q block (64x64), 16 floats per thread
    {
        int row = tid >> 2, cbase = (tid & 3) * 16;
        #pragma unroll
        for (int j = 0; j < 4; j++)
            *(float4*)&Qs[row][cbase + j*4] =
                *(const float4*)&Qg[(size_t)(row0 + row) * DKx + cbase + j*4];
    }
    if (tid < 64) { ml[tid] = -1e30f; ll[tid] = 0.0f; }

    float acc[4][4] = {};

    for (int c0 = 0; c0 < Sx; c0 += 32) {
        // Load K,V blocks (32x64 each), 8 floats per thread per matrix
        {
            int row = tid >> 3, c = (tid & 7) * 8;
            const float* kp = &Kg[(size_t)(c0 + row) * DKx + c];
            const float* vp = &Vg[(size_t)(c0 + row) * DKx + c];
            *(float4*)&Ks[row][c]     = *(const float4*)kp;
            *(float4*)&Ks[row][c + 4] = *(const float4*)(kp + 4);
            *(float4*)&Vs[row][c]     = *(const float4*)vp;
            *(float4*)&Vs[row][c + 4] = *(const float4*)(vp + 4);
        }
        __syncthreads();

        // S = Q K^T * 0.125  (each thread: rows ty*4..+3, cols tx*2..+1)
        float sacc[4][2] = {};
        #pragma unroll
        for (int k = 0; k < DKx; k += 4) {
            float4 qv[4], kv[2];
            #pragma unroll
            for (int i = 0; i < 4; i++) qv[i] = *(const float4*)&Qs[ty*4 + i][k];
            #pragma unroll
            for (int j = 0; j < 2; j++) kv[j] = *(const float4*)&Ks[tx*2 + j][k];
            #pragma unroll
            for (int i = 0; i < 4; i++)
                #pragma unroll
                for (int j = 0; j < 2; j++)
                    sacc[i][j] += qv[i].x*kv[j].x + qv[i].y*kv[j].y
                                + qv[i].z*kv[j].z + qv[i].w*kv[j].w;
        }
        #pragma unroll
        for (int i = 0; i < 4; i++)
            #pragma unroll
            for (int j = 0; j < 2; j++)
                Ss[ty*4 + i][tx*2 + j] = sacc[i][j] * 0.125f;
        __syncthreads();

        // Online softmax per row: warp w owns rows w*8..w*8+7, lane = column
        #pragma unroll
        for (int rr = 0; rr < 8; rr++) {
            int row = warp*8 + rr;
            float sv = Ss[row][lane];
            float mx = sv;
            #pragma unroll
            for (int off = 16; off > 0; off >>= 1)
                mx = fmaxf(mx, __shfl_xor_sync(0xffffffff, mx, off));
            float mprev = ml[row];
            float mnew  = fmaxf(mprev, mx);
            float p     = __expf(sv - mnew);
            float sum   = p;
            #pragma unroll
            for (int off = 16; off > 0; off >>= 1)
                sum += __shfl_xor_sync(0xffffffff, sum, off);
            Ss[row][lane] = p;
            if (lane == 0) {
                float al   = __expf(mprev - mnew);
                al_s[row]  = al;
                ml[row]    = mnew;
                ll[row]    = ll[row] * al + sum;
            }
        }
        __syncthreads();

        // O = al*O + P @ V   (each thread: rows ty*4..+3, cols tx*4..+3)
        #pragma unroll
        for (int i = 0; i < 4; i++) {
            float al = al_s[ty*4 + i];
            acc[i][0] *= al; acc[i][1] *= al; acc[i][2] *= al; acc[i][3] *= al;
        }
        #pragma unroll
        for (int c = 0; c < 32; c++) {
            float4 vv = *(const float4*)&Vs[c][tx*4];
            #pragma unroll
            for (int i = 0; i < 4; i++) {
                float p = Ss[ty*4 + i][c];
                acc[i][0] += p * vv.x;
                acc[i][1] += p * vv.y;
                acc[i][2] += p * vv.z;
                acc[i][3] += p * vv.w;
            }
        }
        __syncthreads();
    }

    // Normalize and write out in [b, s, h, k] layout
    #pragma unroll
    for (int i = 0; i < 4; i++) {
        int row = ty*4 + i;
        float inv = 1.0f / ll[row];
        float4 o = make_float4(acc[i][0]*inv, acc[i][1]*inv, acc[i][2]*inv, acc[i][3]*inv);
        size_t idx = (((size_t)(b*Sx + row0 + row)) * Hx + h) * DKx + tx*4;
        *(float4*)&g_ao[idx] = o;
    }
}

// ---------------------------------------------------------------------------
// Launch
// ---------------------------------------------------------------------------
extern "C" void kernel_launch(void* const* d_in, const int* in_sizes, int n_in,
                              void* d_out, int out_size)
{
    const float* v  = (const float*)d_in[0];
    const float* k  = (const float*)d_in[1];
    const float* q  = (const float*)d_in[2];
    const float* Wq = (const float*)d_in[3];
    const float* bq = (const float*)d_in[4];
    const float* Wk = (const float*)d_in[5];
    const float* bk = (const float*)d_in[6];
    const float* Wv = (const float*)d_in[7];
    const float* bv = (const float*)d_in[8];
    const float* Wo = (const float*)d_in[9];
    const float* bo = (const float*)d_in[10];
    float* out = (float*)d_out;

    dim3 blk(256);
    dim3 gp(Dx / 128, Mx / 128);      // (8, 32) — projections & output GEMM
    dim3 ga(Sx / 64, Bx * Hx);        // (32, 32) — flash attention

    // Projections (bias included), output in [b,h,s,k]
    gemm_kernel<<<gp, blk>>>(q, Wq, bq, nullptr, /*which=*/0, /*asrc=*/0, Dx, Dx);
    gemm_kernel<<<gp, blk>>>(k, Wk, bk, nullptr, /*which=*/1, /*asrc=*/0, Dx, Dx);
    gemm_kernel<<<gp, blk>>>(v, Wv, bv, nullptr, /*which=*/2, /*asrc=*/0, Dx, Dx);

    // Attention with role swap (scores = v2 k2^T, values = q2)
    flash_kernel<<<ga, blk>>>();

    // Output projection: out = g_ao @ Wo^T + bo
    gemm_kernel<<<gp, blk>>>(nullptr, Wo, bo, out, /*which=*/3, /*asrc=*/1, Dx, Dx);
}